// round 7
// baseline (speedup 1.0000x reference)
#include <cuda_runtime.h>
#include <cuda_bf16.h>
#include <cuda_fp8.h>
#include <cstdint>

#define B_Q   256
#define N_MEM 50000
#define D_DIM 1024
#define NTILE 128
#define KC    64                             // fp8 elements per chunk
#define NCHUNK (D_DIM / KC)                  // 16
#define NBLK  ((N_MEM + NTILE - 1) / NTILE)  // 391

// SMEM (dynamic): single-buffered, 128B-padded rows (SW128), data in bytes 0-63
#define SM_Q     0                       // 256 x 128B = 32KB
#define SM_M     32768                   // 128 x 128B = 16KB
#define SM_NORM  49152                   // 128 floats
#define SMEM_TOTAL (SM_NORM + 512)

__device__ unsigned long long g_best[B_Q];
__device__ int g_sel[B_Q];
__device__ uint8_t g_q8[B_Q * D_DIM];

__device__ __forceinline__ uint32_t smem_u32(const void* p) {
    uint32_t a;
    asm("{ .reg .u64 t; cvta.to.shared.u64 t, %1; cvt.u32.u64 %0, t; }" : "=r"(a) : "l"(p));
    return a;
}
__device__ __forceinline__ unsigned int fkey(float f) {
    unsigned int u = __float_as_uint(f);
    return (u & 0x80000000u) ? ~u : (u | 0x80000000u);
}
#define SW128(off) ((off) ^ (((off) >> 3) & 0x70))

#define LDSM_X4(r0, r1, r2, r3, a) \
    asm volatile("ldmatrix.sync.aligned.m8n8.x4.shared.b16 {%0,%1,%2,%3}, [%4];" \
                 : "=r"(r0), "=r"(r1), "=r"(r2), "=r"(r3) : "r"(a))
#define MMA_FP8(d, a, b0, b1) \
    asm volatile("mma.sync.aligned.m16n8k32.row.col.f32.e4m3.e4m3.f32 " \
                 "{%0,%1,%2,%3}, {%4,%5,%6,%7}, {%8,%9}, {%0,%1,%2,%3};" \
                 : "+f"((d)[0]), "+f"((d)[1]), "+f"((d)[2]), "+f"((d)[3]) \
                 : "r"((a)[0]), "r"((a)[1]), "r"((a)[2]), "r"((a)[3]), "r"(b0), "r"(b1))

__device__ __forceinline__ uint32_t pack_fp8x4(float x, float y, float z, float w) {
    __nv_fp8x2_storage_t lo = __nv_cvt_float2_to_fp8x2(make_float2(x, y), __NV_SATFINITE, __NV_E4M3);
    __nv_fp8x2_storage_t hi = __nv_cvt_float2_to_fp8x2(make_float2(z, w), __NV_SATFINITE, __NV_E4M3);
    return (uint32_t)lo | ((uint32_t)hi << 16);
}

// Q fp32 -> e4m3 once; reset g_best.
__global__ __launch_bounds__(256) void prep_kernel(const float* __restrict__ Q) {
    int idx = blockIdx.x * 256 + threadIdx.x;            // one float4 -> 4 fp8
    const float4 v = reinterpret_cast<const float4*>(Q)[idx];
    reinterpret_cast<uint32_t*>(g_q8)[idx] = pack_fp8x4(v.x, v.y, v.z, v.w);
    if (blockIdx.x == 0) g_best[threadIdx.x] = 0ull;
}

// FP8 tensor-core GEMM (256q x 128n x 1024k) + fused row norms + argmax merge.
// Round-3 skeleton: 512 threads, 16 warps (4x4), warp tile 64q x 32n,
// single-buffered smem, register-prefetched Q and M, bulk-sync per chunk.
__global__ __launch_bounds__(512, 1) void simmax_mma(const float* __restrict__ Mptr) {
    extern __shared__ char smem[];
    const uint32_t sb = smem_u32(smem);
    const int tid = threadIdx.x;
    const int l   = tid & 31;
    const int wid = tid >> 5;
    const int wq  = wid >> 2;          // 0..3 : q block of 64
    const int wn  = wid & 3;           // 0..3 : n block of 32
    const int ntile = blockIdx.x * NTILE;

    float* norms = reinterpret_cast<float*>(smem + SM_NORM);

    float acc[4][4][4];
#pragma unroll
    for (int mt = 0; mt < 4; mt++)
#pragma unroll
        for (int nt = 0; nt < 4; nt++)
#pragma unroll
            for (int v = 0; v < 4; v++) acc[mt][nt][v] = 0.0f;

    // M loader: 4 threads/row, 16 floats each (row = tid>>2, quarter = tid&3)
    const int mrow = tid >> 2;
    const int mq4  = tid & 3;
    const int gn   = ntile + mrow;
    const bool mvalid = (gn < N_MEM);
    const float* msrc = Mptr + (size_t)gn * D_DIM + mq4 * 16;
    float4 f[4];
    float sumsq = 0.0f;

    // Q loader: 4 threads/row (row = s>>2, seg = s&3, 16B each), 2 rounds
    uint4 qreg[2];
    const int q0row = tid >> 2,        q0seg = tid & 3;
    const int q1row = (tid + 512) >> 2, q1seg = tid & 3;   // +512: seg unchanged, row+128
    const uint8_t* qsrc0 = g_q8 + (size_t)q0row * D_DIM + q0seg * 16;
    const uint8_t* qsrc1 = g_q8 + (size_t)q1row * D_DIM + q1seg * 16;

    // ---- prologue: prefetch chunk 0 into registers
#pragma unroll
    for (int i = 0; i < 4; i++)
        f[i] = mvalid ? *reinterpret_cast<const float4*>(msrc + i * 4)
                      : make_float4(0.f, 0.f, 0.f, 0.f);
    qreg[0] = *reinterpret_cast<const uint4*>(qsrc0);
    qreg[1] = *reinterpret_cast<const uint4*>(qsrc1);

    const int lrow = l & 15;
    const int lhi  = (l >> 4) * 16;

    for (int c = 0; c < NCHUNK; c++) {
        // ---- STS Q(c) from regs
        {
            uint32_t off0 = (uint32_t)(q0row * 128 + q0seg * 16);
            uint32_t off1 = (uint32_t)(q1row * 128 + q1seg * 16);
            *reinterpret_cast<uint4*>(smem + SM_Q + SW128(off0)) = qreg[0];
            *reinterpret_cast<uint4*>(smem + SM_Q + SW128(off1)) = qreg[1];
        }
        // ---- STS M(c): fp32 -> e4m3 + fused sumsq (16 floats -> 16B)
        {
            uint32_t w[4];
#pragma unroll
            for (int i = 0; i < 4; i++) {
                sumsq += f[i].x * f[i].x + f[i].y * f[i].y + f[i].z * f[i].z + f[i].w * f[i].w;
                w[i] = pack_fp8x4(f[i].x, f[i].y, f[i].z, f[i].w);
            }
            uint32_t off = (uint32_t)(mrow * 128 + mq4 * 16);
            *reinterpret_cast<uint4*>(smem + SM_M + SW128(off)) = *reinterpret_cast<uint4*>(&w[0]);
        }
        __syncthreads();   // chunk c staged

        // ---- prefetch chunk c+1 (hidden under MMAs below)
        if (c + 1 < NCHUNK) {
#pragma unroll
            for (int i = 0; i < 4; i++)
                f[i] = mvalid ? *reinterpret_cast<const float4*>(msrc + (c + 1) * KC + i * 4)
                              : make_float4(0.f, 0.f, 0.f, 0.f);
            qreg[0] = *reinterpret_cast<const uint4*>(qsrc0 + (c + 1) * KC);
            qreg[1] = *reinterpret_cast<const uint4*>(qsrc1 + (c + 1) * KC);
        }

        // ---- compute chunk c: 2 k32 steps
#pragma unroll
        for (int ks = 0; ks < 2; ks++) {
            uint32_t b[4], b2[4];
            {
                uint32_t off = (uint32_t)((wn * 32 + lrow) * 128 + ks * 32 + lhi);
                LDSM_X4(b[0], b[1], b[2], b[3], sb + SM_M + SW128(off));
            }
            {
                uint32_t off = (uint32_t)((wn * 32 + 16 + lrow) * 128 + ks * 32 + lhi);
                LDSM_X4(b2[0], b2[1], b2[2], b2[3], sb + SM_M + SW128(off));
            }
#pragma unroll
            for (int mt = 0; mt < 4; mt++) {
                uint32_t a[4];
                uint32_t off = (uint32_t)((wq * 64 + mt * 16 + lrow) * 128 + ks * 32 + lhi);
                LDSM_X4(a[0], a[1], a[2], a[3], sb + SM_Q + SW128(off));
                MMA_FP8(acc[mt][0], a, b[0],  b[2]);
                MMA_FP8(acc[mt][1], a, b[1],  b[3]);
                MMA_FP8(acc[mt][2], a, b2[0], b2[2]);
                MMA_FP8(acc[mt][3], a, b2[1], b2[3]);
            }
        }
        __syncthreads();   // all reads done; safe to overwrite smem
    }

    // ---- row norms (4 threads/row, fp32 exact)
    sumsq += __shfl_xor_sync(0xFFFFFFFFu, sumsq, 1);
    sumsq += __shfl_xor_sync(0xFFFFFFFFu, sumsq, 2);
    if (mq4 == 0) norms[mrow] = rsqrtf(fmaxf(sumsq, 1e-30f));
    __syncthreads();
    const float* invn = norms;

    // ---- epilogue: per-q-row argmax over this CTA's 128 n
#pragma unroll
    for (int mt = 0; mt < 4; mt++) {
#pragma unroll
        for (int sub = 0; sub < 2; sub++) {
            unsigned long long best = 0ull;
#pragma unroll
            for (int nt = 0; nt < 4; nt++) {
#pragma unroll
                for (int cc = 0; cc < 2; cc++) {
                    int nl = wn * 32 + nt * 8 + 2 * (l & 3) + cc;
                    int n = ntile + nl;
                    if (n < N_MEM) {
                        float s = acc[mt][nt][sub * 2 + cc] * invn[nl];
                        unsigned long long key =
                            ((unsigned long long)fkey(s) << 32) |
                            (unsigned long long)(unsigned int)(~(unsigned int)n);
                        if (key > best) best = key;
                    }
                }
            }
            unsigned long long o;
            o = __shfl_xor_sync(0xFFFFFFFFu, best, 1); if (o > best) best = o;
            o = __shfl_xor_sync(0xFFFFFFFFu, best, 2); if (o > best) best = o;
            if ((l & 3) == 0) {
                int q = wq * 64 + mt * 16 + (l >> 2) + sub * 8;
                atomicMax(&g_best[q], best);
            }
        }
    }
}

// Exact fp32 recompute of the winner's cosine sim + threshold.
__global__ __launch_bounds__(256) void finalize_kernel(const float* __restrict__ Q,
                                                       const float* __restrict__ M) {
    __shared__ float sdq[256], sdm[256], sdp[256];
    const int b = blockIdx.x;
    const int tid = threadIdx.x;

    unsigned long long pk = g_best[b];
    int idx = (int)(~(unsigned int)(pk & 0xFFFFFFFFull));

    const float* q = Q + (size_t)b * D_DIM;
    const float* m = M + (size_t)idx * D_DIM;
    float dq = 0.f, dm = 0.f, dp = 0.f;
    for (int k = tid * 4; k < D_DIM; k += 256 * 4) {
        float4 qa = *reinterpret_cast<const float4*>(&q[k]);
        float4 mb = *reinterpret_cast<const float4*>(&m[k]);
        dq += qa.x * qa.x + qa.y * qa.y + qa.z * qa.z + qa.w * qa.w;
        dm += mb.x * mb.x + mb.y * mb.y + mb.z * mb.z + mb.w * mb.w;
        dp += qa.x * mb.x + qa.y * mb.y + qa.z * mb.z + qa.w * mb.w;
    }
    sdq[tid] = dq; sdm[tid] = dm; sdp[tid] = dp;
    __syncthreads();
    for (int s = 128; s > 0; s >>= 1) {
        if (tid < s) {
            sdq[tid] += sdq[tid + s];
            sdm[tid] += sdm[tid + s];
            sdp[tid] += sdp[tid + s];
        }
        __syncthreads();
    }
    if (tid == 0) {
        float sim = sdp[0] / fmaxf(sqrtf(sdq[0]) * sqrtf(sdm[0]), 1e-8f);
        g_sel[b] = (sim > 0.6f) ? idx : -1;
    }
}

__global__ __launch_bounds__(128) void decode_kernel(const float* __restrict__ M,
                                                     const float* __restrict__ W,
                                                     const float* __restrict__ bias,
                                                     float* __restrict__ out) {
    const int b = blockIdx.y;
    const int j = blockIdx.x * 128 + threadIdx.x;
    const int sel = g_sel[b];
    float r = 0.0f;
    if (sel >= 0) {
        const float* e = M + (size_t)sel * D_DIM;
        const float* w = W + (size_t)j * D_DIM;
        float s = 0.0f;
        for (int k = 0; k < D_DIM; k += 4) {
            float4 ev = *reinterpret_cast<const float4*>(&e[k]);
            float4 wv = *reinterpret_cast<const float4*>(&w[k]);
            s += ev.x * wv.x + ev.y * wv.y + ev.z * wv.z + ev.w * wv.w;
        }
        r = s + bias[j];
    }
    out[(size_t)b * D_DIM + j] = r;
}

extern "C" void kernel_launch(void* const* d_in, const int* in_sizes, int n_in,
                              void* d_out, int out_size) {
    const float* Q    = (const float*)d_in[0];
    const float* M    = (const float*)d_in[1];
    const float* W    = (const float*)d_in[2];
    const float* bias = (const float*)d_in[3];
    float* out = (float*)d_out;

    cudaFuncSetAttribute(simmax_mma, cudaFuncAttributeMaxDynamicSharedMemorySize, SMEM_TOTAL);

    prep_kernel<<<B_Q * D_DIM / 4 / 256, 256>>>(Q);
    simmax_mma<<<NBLK, 512, SMEM_TOTAL>>>(M);
    finalize_kernel<<<B_Q, 256>>>(Q, M);
    decode_kernel<<<dim3(D_DIM / 128, B_Q), 128>>>(M, W, bias, out);
}

// round 8
// speedup vs baseline: 1.4403x; 1.4403x over previous
#include <cuda_runtime.h>
#include <cuda_fp16.h>
#include <cstdint>

#define B_Q   256
#define N_MEM 50000
#define D_DIM 1024
#define NTILE 128
#define KC    64                             // f16 elements per chunk (128B row)
#define NCHUNK (D_DIM / KC)                  // 16
#define NBLK  ((N_MEM + NTILE - 1) / NTILE)  // 391

// SMEM (dynamic): single-buffered
#define SM_Q     0                       // 256 x 128B = 32KB
#define SM_M     32768                   // 128 x 128B = 16KB
#define SM_NORM  49152                   // 128 floats
#define SMEM_TOTAL (SM_NORM + 512)

__device__ unsigned long long g_best[B_Q];
__device__ int g_sel[B_Q];
__device__ __half g_qh[B_Q * D_DIM];

__device__ __forceinline__ uint32_t smem_u32(const void* p) {
    uint32_t a;
    asm("{ .reg .u64 t; cvta.to.shared.u64 t, %1; cvt.u32.u64 %0, t; }" : "=r"(a) : "l"(p));
    return a;
}
__device__ __forceinline__ unsigned int fkey(float f) {
    unsigned int u = __float_as_uint(f);
    return (u & 0x80000000u) ? ~u : (u | 0x80000000u);
}
#define SW128(off) ((off) ^ (((off) >> 3) & 0x70))

#define LDSM_X4(r0, r1, r2, r3, a) \
    asm volatile("ldmatrix.sync.aligned.m8n8.x4.shared.b16 {%0,%1,%2,%3}, [%4];" \
                 : "=r"(r0), "=r"(r1), "=r"(r2), "=r"(r3) : "r"(a))
#define LDSM_X4_T(r0, r1, r2, r3, a) \
    asm volatile("ldmatrix.sync.aligned.m8n8.x4.trans.shared.b16 {%0,%1,%2,%3}, [%4];" \
                 : "=r"(r0), "=r"(r1), "=r"(r2), "=r"(r3) : "r"(a))
// f16 inputs, f16 accumulators (2 regs = 4 halves)
#define MMA_F16(d, a, b0, b1) \
    asm volatile("mma.sync.aligned.m16n8k16.row.col.f16.f16.f16.f16 " \
                 "{%0,%1}, {%2,%3,%4,%5}, {%6,%7}, {%0,%1};" \
                 : "+r"((d)[0]), "+r"((d)[1]) \
                 : "r"((a)[0]), "r"((a)[1]), "r"((a)[2]), "r"((a)[3]), "r"(b0), "r"(b1))

__device__ __forceinline__ uint32_t pack_h2(float x, float y) {
    __half2 h = __floats2half2_rn(x, y);
    return *reinterpret_cast<uint32_t*>(&h);
}

// Q fp32 -> f16 once; reset g_best.
__global__ __launch_bounds__(256) void prep_kernel(const float* __restrict__ Q) {
    int idx = blockIdx.x * 256 + threadIdx.x;            // one float4 each
    const float4 v = reinterpret_cast<const float4*>(Q)[idx];
    uint2 w;
    w.x = pack_h2(v.x, v.y);
    w.y = pack_h2(v.z, v.w);
    reinterpret_cast<uint2*>(g_qh)[idx] = w;
    if (blockIdx.x == 0) g_best[threadIdx.x] = 0ull;
}

// f16 tensor-core GEMM (256q x 128n x 1024k), f16 accum, fused row norms + argmax.
// 512 threads, 16 warps (4 wq x 4 wn), warp tile 64q x 32n, single-buffer bulk-sync.
__global__ __launch_bounds__(512, 1) void simmax_mma(const float* __restrict__ Mptr) {
    extern __shared__ char smem[];
    const uint32_t sb = smem_u32(smem);
    const int tid = threadIdx.x;
    const int l   = tid & 31;
    const int wid = tid >> 5;
    const int wq  = wid >> 2;          // 0..3 : q block of 64
    const int wn  = wid & 3;           // 0..3 : n block of 32
    const int ntile = blockIdx.x * NTILE;

    float* norms = reinterpret_cast<float*>(smem + SM_NORM);

    uint32_t acc[4][4][2];             // f16x2 accumulators
#pragma unroll
    for (int mt = 0; mt < 4; mt++)
#pragma unroll
        for (int nt = 0; nt < 4; nt++) {
            acc[mt][nt][0] = 0u;
            acc[mt][nt][1] = 0u;
        }

    // M loader: 4 threads/row, 16 floats each
    const int mrow = tid >> 2;
    const int mq4  = tid & 3;
    const int gn   = ntile + mrow;
    const bool mvalid = (gn < N_MEM);
    const float* msrc = Mptr + (size_t)gn * D_DIM + mq4 * 16;
    float4 f[4];
    float sumsq = 0.0f;

    // Q loader: 2048 16B segs per chunk, 4 per thread (rows tid>>2 and +128)
    uint4 qreg[2];
    const int q0row = tid >> 2,         qseg = tid & 3;
    const int q1row = q0row + 128;
    const __half* qsrc0 = g_qh + (size_t)q0row * D_DIM + qseg * 8;   // 8 halves = 16B
    const __half* qsrc1 = g_qh + (size_t)q1row * D_DIM + qseg * 8;

    // ---- prologue: prefetch chunk 0
#pragma unroll
    for (int i = 0; i < 4; i++)
        f[i] = mvalid ? *reinterpret_cast<const float4*>(msrc + i * 4)
                      : make_float4(0.f, 0.f, 0.f, 0.f);
    qreg[0] = *reinterpret_cast<const uint4*>(qsrc0);
    qreg[1] = *reinterpret_cast<const uint4*>(qsrc1);

    const int lrow = l & 15;
    const int lhi  = (l >> 4) * 16;

    for (int c = 0; c < NCHUNK; c++) {
        // ---- STS Q(c) from regs (16B per row-slot, 4 slots of 16B per 128B row)
        {
            uint32_t off0 = (uint32_t)(q0row * 128 + qseg * 16 + 0);
            uint32_t off1 = (uint32_t)(q1row * 128 + qseg * 16 + 0);
            // each row is 64 f16 = 128B; thread covers 16B at qseg*16 and qseg*16+64
            *reinterpret_cast<uint4*>(smem + SM_Q + SW128((uint32_t)(q0row * 128 + qseg * 16)))       = qreg[0];
            *reinterpret_cast<uint4*>(smem + SM_Q + SW128((uint32_t)(q1row * 128 + qseg * 16)))       = qreg[1];
            (void)off0; (void)off1;
        }
        // wait: a row is 128B = 8 segs of 16B but we assigned 4 segs/row... rows are
        // covered by 4 threads x 16B = 64B?? No: row = 64 f16 = 128 BYTES, segs 0..7.
        // Mapping fix: 512 threads x 4 iterations cover 2048 segs; do explicit loop:
        __syncthreads();   // placeholder sync replaced below (see full staging)

        // (dead code guard — real staging below)
        break;
    }

    // ===================== REAL LOOP (correct staging) ======================
    // Redo cleanly: Q chunk = 256 rows x 128B = 2048 segs; thread covers segs
    // tid and tid+512, ... (4 total). M as before.
    {
        // reset accumulators (loop above broke immediately; acc untouched, sumsq=0)
        const int s0 = tid, s1 = tid + 512, s2 = tid + 1024, s3 = tid + 1536;
        const int qr[4] = { s0 >> 3, s1 >> 3, s2 >> 3, s3 >> 3 };
        const int qs[4] = { s0 & 7,  s1 & 7,  s2 & 7,  s3 & 7 };
        uint4 qq[4];
#pragma unroll
        for (int i = 0; i < 4; i++)
            qq[i] = *reinterpret_cast<const uint4*>(g_qh + (size_t)qr[i] * D_DIM + qs[i] * 8);

        for (int c = 0; c < NCHUNK; c++) {
            // ---- STS Q(c)
#pragma unroll
            for (int i = 0; i < 4; i++) {
                uint32_t off = (uint32_t)(qr[i] * 128 + qs[i] * 16);
                *reinterpret_cast<uint4*>(smem + SM_Q + SW128(off)) = qq[i];
            }
            // ---- STS M(c): fp32 -> f16 + fused sumsq
            {
                uint32_t w[8];
#pragma unroll
                for (int i = 0; i < 4; i++) {
                    sumsq += f[i].x * f[i].x + f[i].y * f[i].y + f[i].z * f[i].z + f[i].w * f[i].w;
                    w[i * 2]     = pack_h2(f[i].x, f[i].y);
                    w[i * 2 + 1] = pack_h2(f[i].z, f[i].w);
                }
                uint32_t off = (uint32_t)(mrow * 128 + mq4 * 32);
                *reinterpret_cast<uint4*>(smem + SM_M + SW128(off))      = *reinterpret_cast<uint4*>(&w[0]);
                *reinterpret_cast<uint4*>(smem + SM_M + SW128(off + 16)) = *reinterpret_cast<uint4*>(&w[4]);
            }
            __syncthreads();

            // ---- prefetch chunk c+1
            if (c + 1 < NCHUNK) {
#pragma unroll
                for (int i = 0; i < 4; i++)
                    f[i] = mvalid ? *reinterpret_cast<const float4*>(msrc + (c + 1) * KC + i * 4)
                                  : make_float4(0.f, 0.f, 0.f, 0.f);
#pragma unroll
                for (int i = 0; i < 4; i++)
                    qq[i] = *reinterpret_cast<const uint4*>(
                        g_qh + (size_t)qr[i] * D_DIM + (c + 1) * KC + qs[i] * 8);
            }

            // ---- compute chunk c: 4 k16 steps
#pragma unroll
            for (int ks = 0; ks < 4; ks++) {
                uint32_t b[2][4];
#pragma unroll
                for (int p = 0; p < 2; p++) {
                    uint32_t off = (uint32_t)((wn * 32 + p * 16 + lrow) * 128 + ks * 32 + lhi);
                    LDSM_X4_T(b[p][0], b[p][1], b[p][2], b[p][3], sb + SM_M + SW128(off));
                }
#pragma unroll
                for (int mt = 0; mt < 4; mt++) {
                    uint32_t a[4];
                    uint32_t off = (uint32_t)((wq * 64 + mt * 16 + lrow) * 128 + ks * 32 + lhi);
                    LDSM_X4(a[0], a[1], a[2], a[3], sb + SM_Q + SW128(off));
#pragma unroll
                    for (int nt = 0; nt < 4; nt++)
                        MMA_F16(acc[mt][nt], a, b[nt >> 1][nt & 1], b[nt >> 1][(nt & 1) + 2]);
                }
            }
            __syncthreads();
        }
    }

    // ---- row norms (4 threads/row, fp32 exact)
    sumsq += __shfl_xor_sync(0xFFFFFFFFu, sumsq, 1);
    sumsq += __shfl_xor_sync(0xFFFFFFFFu, sumsq, 2);
    if (mq4 == 0) norms[mrow] = rsqrtf(fmaxf(sumsq, 1e-30f));
    __syncthreads();
    const float* invn = norms;

    // ---- epilogue: per-q-row argmax over this CTA's 128 n
    // acc reg0 = rows (l>>2), reg1 = rows (l>>2)+8; halves = cols 2*(l&3), +1
#pragma unroll
    for (int mt = 0; mt < 4; mt++) {
#pragma unroll
        for (int sub = 0; sub < 2; sub++) {
            unsigned long long best = 0ull;
#pragma unroll
            for (int nt = 0; nt < 4; nt++) {
                __half2 h = *reinterpret_cast<__half2*>(&acc[mt][nt][sub]);
                float2 fv = __half22float2(h);
#pragma unroll
                for (int cc = 0; cc < 2; cc++) {
                    int nl = wn * 32 + nt * 8 + 2 * (l & 3) + cc;
                    int n = ntile + nl;
                    if (n < N_MEM) {
                        float s = (cc == 0 ? fv.x : fv.y) * invn[nl];
                        unsigned long long key =
                            ((unsigned long long)fkey(s) << 32) |
                            (unsigned long long)(unsigned int)(~(unsigned int)n);
                        if (key > best) best = key;
                    }
                }
            }
            unsigned long long o;
            o = __shfl_xor_sync(0xFFFFFFFFu, best, 1); if (o > best) best = o;
            o = __shfl_xor_sync(0xFFFFFFFFu, best, 2); if (o > best) best = o;
            if ((l & 3) == 0) {
                int q = wq * 64 + mt * 16 + (l >> 2) + sub * 8;
                atomicMax(&g_best[q], best);
            }
        }
    }
}

// Exact fp32 recompute of the winner's cosine sim + threshold.
__global__ __launch_bounds__(256) void finalize_kernel(const float* __restrict__ Q,
                                                       const float* __restrict__ M) {
    __shared__ float sdq[256], sdm[256], sdp[256];
    const int b = blockIdx.x;
    const int tid = threadIdx.x;

    unsigned long long pk = g_best[b];
    int idx = (int)(~(unsigned int)(pk & 0xFFFFFFFFull));

    const float* q = Q + (size_t)b * D_DIM;
    const float* m = M + (size_t)idx * D_DIM;
    float dq = 0.f, dm = 0.f, dp = 0.f;
    for (int k = tid * 4; k < D_DIM; k += 256 * 4) {
        float4 qa = *reinterpret_cast<const float4*>(&q[k]);
        float4 mb = *reinterpret_cast<const float4*>(&m[k]);
        dq += qa.x * qa.x + qa.y * qa.y + qa.z * qa.z + qa.w * qa.w;
        dm += mb.x * mb.x + mb.y * mb.y + mb.z * mb.z + mb.w * mb.w;
        dp += qa.x * mb.x + qa.y * mb.y + qa.z * mb.z + qa.w * mb.w;
    }
    sdq[tid] = dq; sdm[tid] = dm; sdp[tid] = dp;
    __syncthreads();
    for (int s = 128; s > 0; s >>= 1) {
        if (tid < s) {
            sdq[tid] += sdq[tid + s];
            sdm[tid] += sdm[tid + s];
            sdp[tid] += sdp[tid + s];
        }
        __syncthreads();
    }
    if (tid == 0) {
        float sim = sdp[0] / fmaxf(sqrtf(sdq[0]) * sqrtf(sdm[0]), 1e-8f);
        g_sel[b] = (sim > 0.6f) ? idx : -1;
    }
}

__global__ __launch_bounds__(128) void decode_kernel(const float* __restrict__ M,
                                                     const float* __restrict__ W,
                                                     const float* __restrict__ bias,
                                                     float* __restrict__ out) {
    const int b = blockIdx.y;
    const int j = blockIdx.x * 128 + threadIdx.x;
    const int sel = g_sel[b];
    float r = 0.0f;
    if (sel >= 0) {
        const float* e = M + (size_t)sel * D_DIM;
        const float* w = W + (size_t)j * D_DIM;
        float s = 0.0f;
        for (int k = 0; k < D_DIM; k += 4) {
            float4 ev = *reinterpret_cast<const float4*>(&e[k]);
            float4 wv = *reinterpret_cast<const float4*>(&w[k]);
            s += ev.x * wv.x + ev.y * wv.y + ev.z * wv.z + ev.w * wv.w;
        }
        r = s + bias[j];
    }
    out[(size_t)b * D_DIM + j] = r;
}

extern "C" void kernel_launch(void* const* d_in, const int* in_sizes, int n_in,
                              void* d_out, int out_size) {
    const float* Q    = (const float*)d_in[0];
    const float* M    = (const float*)d_in[1];
    const float* W    = (const float*)d_in[2];
    const float* bias = (const float*)d_in[3];
    float* out = (float*)d_out;

    cudaFuncSetAttribute(simmax_mma, cudaFuncAttributeMaxDynamicSharedMemorySize, SMEM_TOTAL);

    prep_kernel<<<B_Q * D_DIM / 4 / 256, 256>>>(Q);
    simmax_mma<<<NBLK, 512, SMEM_TOTAL>>>(M);
    finalize_kernel<<<B_Q, 256>>>(Q, M);
    decode_kernel<<<dim3(D_DIM / 128, B_Q), 128>>>(M, W, bias, out);
}